// round 1
// baseline (speedup 1.0000x reference)
#include <cuda_runtime.h>
#include <math.h>

// Problem constants
#define NTOK 2048          // B*T = 2*1024
#define SEQ  1024
#define DMODEL 768
#define NHEAD 12
#define HDIM 64
#define NLAYER 8
#define VOCAB 50257

// ---------------- scratch (device globals; no allocation allowed) ------------
__device__ float g_x   [NTOK * DMODEL];      // residual stream
__device__ float g_h   [NTOK * DMODEL];      // layernorm output
__device__ float g_qkv [NTOK * 3 * DMODEL];  // qkv projection
__device__ float g_y   [NTOK * DMODEL];      // attention output
__device__ float g_m   [NTOK * 4 * DMODEL];  // mlp hidden
__device__ float g_rowloss[NTOK];

// ---------------- helpers ----------------------------------------------------
__device__ __forceinline__ float gelu_f(float x) {
    const float c = 0.7978845608028654f; // sqrt(2/pi)
    float x3 = x * x * x;
    return 0.5f * x * (1.0f + tanhf(c * (x + 0.044715f * x3)));
}

// ---------------- embedding --------------------------------------------------
__global__ void embed_kernel(const int* __restrict__ idx,
                             const float* __restrict__ wte,
                             const float* __restrict__ wpe) {
    int row = blockIdx.x;           // 0..2047
    int t   = row & (SEQ - 1);
    int tok = idx[row];
    const float* we = wte + (size_t)tok * DMODEL;
    const float* wp = wpe + (size_t)t   * DMODEL;
    float* xr = g_x + (size_t)row * DMODEL;
    for (int d = threadIdx.x; d < DMODEL; d += blockDim.x)
        xr[d] = we[d] + wp[d];
}

// ---------------- layernorm (256 threads, 3 elems/thread) --------------------
__global__ void __launch_bounds__(256) ln_kernel(const float* __restrict__ x,
                                                 const float* __restrict__ sc,
                                                 const float* __restrict__ bi,
                                                 float* __restrict__ out) {
    __shared__ float red[8];
    int row = blockIdx.x, tid = threadIdx.x;
    const float* xr = x + (size_t)row * DMODEL;
    float v0 = xr[tid], v1 = xr[tid + 256], v2 = xr[tid + 512];

    // sum reduce
    float s = v0 + v1 + v2;
    #pragma unroll
    for (int o = 16; o > 0; o >>= 1) s += __shfl_xor_sync(~0u, s, o);
    if ((tid & 31) == 0) red[tid >> 5] = s;
    __syncthreads();
    if (tid < 32) {
        float t = (tid < 8) ? red[tid] : 0.f;
        #pragma unroll
        for (int o = 4; o > 0; o >>= 1) t += __shfl_xor_sync(~0u, t, o);
        if (tid == 0) red[0] = t;
    }
    __syncthreads();
    float mu = red[0] * (1.0f / DMODEL);
    __syncthreads();

    float d0 = v0 - mu, d1 = v1 - mu, d2 = v2 - mu;
    float s2 = d0 * d0 + d1 * d1 + d2 * d2;
    #pragma unroll
    for (int o = 16; o > 0; o >>= 1) s2 += __shfl_xor_sync(~0u, s2, o);
    if ((tid & 31) == 0) red[tid >> 5] = s2;
    __syncthreads();
    if (tid < 32) {
        float t = (tid < 8) ? red[tid] : 0.f;
        #pragma unroll
        for (int o = 4; o > 0; o >>= 1) t += __shfl_xor_sync(~0u, t, o);
        if (tid == 0) red[0] = t;
    }
    __syncthreads();
    float var = red[0] * (1.0f / DMODEL);
    float rs  = rsqrtf(var + 1e-5f);

    float* orow = out + (size_t)row * DMODEL;
    orow[tid]       = d0 * rs * sc[tid]       + bi[tid];
    orow[tid + 256] = d1 * rs * sc[tid + 256] + bi[tid + 256];
    orow[tid + 512] = d2 * rs * sc[tid + 512] + bi[tid + 512];
}

// ---------------- SGEMM 128x128x8, 256 threads, 8x8/thread -------------------
// A: [M,K] row-major. B: TRANSB ? [N,K] : [K,N] row-major. C: [M,N] row-major.
// EPI: 0 -> C = acc
//      1 -> C = acc + bias
//      2 -> C = gelu(acc + bias)
//      3 -> C = C + acc + bias   (residual accumulate)
template <bool TRANSB, int EPI>
__global__ void __launch_bounds__(256) sgemm_kernel(
    const float* __restrict__ A, const float* __restrict__ B,
    const float* __restrict__ bias, float* __restrict__ C,
    int M, int N, int K) {
    __shared__ float As[8][128];
    __shared__ float Bs[8][128];

    int tid = threadIdx.x;
    int bm = blockIdx.y * 128, bn = blockIdx.x * 128;

    int arow = tid >> 1;             // 0..127
    int acol = (tid & 1) * 4;        // 0 or 4
    int brow = tid >> 5;             // 0..7   (NN)
    int bcol = (tid & 31) * 4;       // 0..124 (NN)
    int tx = tid & 15, ty = tid >> 4;

    float acc[8][8];
    #pragma unroll
    for (int i = 0; i < 8; i++)
        #pragma unroll
        for (int j = 0; j < 8; j++) acc[i][j] = 0.f;

    for (int k0 = 0; k0 < K; k0 += 8) {
        float4 av = *(const float4*)(A + (size_t)(bm + arow) * K + k0 + acol);
        float4 bv;
        if (TRANSB) {
            bool ok = (bn + arow) < N;
            bv = ok ? *(const float4*)(B + (size_t)(bn + arow) * K + k0 + acol)
                    : make_float4(0.f, 0.f, 0.f, 0.f);
        } else {
            bv = *(const float4*)(B + (size_t)(k0 + brow) * N + bn + bcol);
        }
        __syncthreads();
        As[acol + 0][arow] = av.x;
        As[acol + 1][arow] = av.y;
        As[acol + 2][arow] = av.z;
        As[acol + 3][arow] = av.w;
        if (TRANSB) {
            Bs[acol + 0][arow] = bv.x;
            Bs[acol + 1][arow] = bv.y;
            Bs[acol + 2][arow] = bv.z;
            Bs[acol + 3][arow] = bv.w;
        } else {
            *(float4*)&Bs[brow][bcol] = bv;
        }
        __syncthreads();

        #pragma unroll
        for (int kk = 0; kk < 8; kk++) {
            float a[8], b[8];
            *(float4*)(a)     = *(const float4*)&As[kk][ty * 4];
            *(float4*)(a + 4) = *(const float4*)&As[kk][64 + ty * 4];
            *(float4*)(b)     = *(const float4*)&Bs[kk][tx * 4];
            *(float4*)(b + 4) = *(const float4*)&Bs[kk][64 + tx * 4];
            #pragma unroll
            for (int i = 0; i < 8; i++)
                #pragma unroll
                for (int j = 0; j < 8; j++)
                    acc[i][j] += a[i] * b[j];
        }
    }

    #pragma unroll
    for (int i = 0; i < 8; i++) {
        int row = bm + ((i < 4) ? (ty * 4 + i) : (64 + ty * 4 + i - 4));
        #pragma unroll
        for (int j = 0; j < 8; j++) {
            int col = bn + ((j < 4) ? (tx * 4 + j) : (64 + tx * 4 + j - 4));
            if (TRANSB && col >= N) continue;
            float v = acc[i][j];
            if (EPI >= 1) v += bias[col];
            if (EPI == 2) v = gelu_f(v);
            size_t off = (size_t)row * N + col;
            if (EPI == 3) v += C[off];
            C[off] = v;
        }
    }
}

// ---------------- flash-style causal attention -------------------------------
// grid: (T/64, H, B), 256 threads. 64 q-rows/block, 32 kv-rows/tile.
// thread t: q-row r = t>>2, sub j = t&3; owns out dims [j*16, j*16+16),
// score cols [j*8, j*8+8) per tile.
__global__ void __launch_bounds__(256) attn_kernel(float* __restrict__ out) {
    __shared__ float qs[64][64];
    __shared__ float ks[32][64];
    __shared__ float vs[32][64];
    __shared__ float ps[64][32];

    int q0 = blockIdx.x * 64;
    int h  = blockIdx.y;
    int b  = blockIdx.z;
    int tid = threadIdx.x;
    int r = tid >> 2, j = tid & 3;
    int d0 = j * 16, c0 = j * 8;
    const float scale = 0.125f; // 1/sqrt(64)

    // load q tile (pre-scaled)
    {
        int lr = tid >> 2;
        int cc = (tid & 3) * 16;
        const float* src = g_qkv + (size_t)(b * SEQ + q0 + lr) * (3 * DMODEL) + h * HDIM + cc;
        #pragma unroll
        for (int i = 0; i < 4; i++) {
            float4 v = ((const float4*)src)[i];
            qs[lr][cc + i * 4 + 0] = v.x * scale;
            qs[lr][cc + i * 4 + 1] = v.y * scale;
            qs[lr][cc + i * 4 + 2] = v.z * scale;
            qs[lr][cc + i * 4 + 3] = v.w * scale;
        }
    }

    float oacc[16];
    #pragma unroll
    for (int d = 0; d < 16; d++) oacc[d] = 0.f;
    float mrun = -1e30f, lrun = 0.f;

    for (int kv0 = 0; kv0 < q0 + 64; kv0 += 32) {
        __syncthreads(); // previous tile fully consumed (also covers initial q load)
        {
            int lr2 = tid >> 3;          // 0..31
            int cc  = (tid & 7) * 8;     // 0..56
            const float* ksrc = g_qkv + (size_t)(b * SEQ + kv0 + lr2) * (3 * DMODEL) + DMODEL     + h * HDIM + cc;
            const float* vsrc = g_qkv + (size_t)(b * SEQ + kv0 + lr2) * (3 * DMODEL) + 2 * DMODEL + h * HDIM + cc;
            *(float4*)&ks[lr2][cc]     = ((const float4*)ksrc)[0];
            *(float4*)&ks[lr2][cc + 4] = ((const float4*)ksrc)[1];
            *(float4*)&vs[lr2][cc]     = ((const float4*)vsrc)[0];
            *(float4*)&vs[lr2][cc + 4] = ((const float4*)vsrc)[1];
        }
        __syncthreads();

        // scores for my 8 columns
        float sv[8];
        #pragma unroll
        for (int c = 0; c < 8; c++) {
            int ci = c0 + c;
            float a = 0.f;
            #pragma unroll 16
            for (int d = 0; d < 64; d++) a += qs[r][d] * ks[ci][d];
            sv[c] = (kv0 + ci <= q0 + r) ? a : -1e30f;
        }
        // tile max across 8 + the 4 lanes of this row (consecutive lanes, 4-aligned)
        float tm = sv[0];
        #pragma unroll
        for (int c = 1; c < 8; c++) tm = fmaxf(tm, sv[c]);
        tm = fmaxf(tm, __shfl_xor_sync(~0u, tm, 1));
        tm = fmaxf(tm, __shfl_xor_sync(~0u, tm, 2));
        float mnew  = fmaxf(mrun, tm);
        float alpha = __expf(mrun - mnew);
        float psum = 0.f;
        #pragma unroll
        for (int c = 0; c < 8; c++) {
            float p = __expf(sv[c] - mnew);
            ps[r][c0 + c] = p;
            psum += p;
        }
        psum += __shfl_xor_sync(~0u, psum, 1);
        psum += __shfl_xor_sync(~0u, psum, 2);
        lrun = lrun * alpha + psum;
        mrun = mnew;
        #pragma unroll
        for (int d = 0; d < 16; d++) oacc[d] *= alpha;
        __syncwarp();
        #pragma unroll 4
        for (int c = 0; c < 32; c++) {
            float p = ps[r][c];
            #pragma unroll
            for (int d = 0; d < 16; d++) oacc[d] += p * vs[c][d0 + d];
        }
    }

    float inv = 1.0f / lrun;
    float* orow = out + (size_t)(b * SEQ + q0 + r) * DMODEL + h * HDIM + d0;
    #pragma unroll
    for (int d = 0; d < 16; d++) orow[d] = oacc[d] * inv;
}

// ---------------- loss: per-row online logsumexp -----------------------------
__global__ void __launch_bounds__(256) lossrow_kernel(const float* __restrict__ logits,
                                                      const int* __restrict__ targets) {
    int row = blockIdx.x;
    const float* lr_ = logits + (size_t)row * VOCAB;
    float m = -1e30f, s = 0.f;
    for (int jv = threadIdx.x; jv < VOCAB; jv += 256) {
        float v = lr_[jv];
        if (v <= m) {
            s += __expf(v - m);
        } else {
            s = s * __expf(m - v) + 1.0f;
            m = v;
        }
    }
    __shared__ float sm[256], ss[256];
    sm[threadIdx.x] = m; ss[threadIdx.x] = s;
    __syncthreads();
    for (int st = 128; st > 0; st >>= 1) {
        if (threadIdx.x < st) {
            float ma = sm[threadIdx.x],      sa = ss[threadIdx.x];
            float mb = sm[threadIdx.x + st], sb = ss[threadIdx.x + st];
            float M  = fmaxf(ma, mb);
            ss[threadIdx.x] = sa * __expf(ma - M) + sb * __expf(mb - M);
            sm[threadIdx.x] = M;
        }
        __syncthreads();
    }
    if (threadIdx.x == 0) {
        float lse = sm[0] + logf(ss[0]);
        g_rowloss[row] = lse - lr_[targets[row]];
    }
}

__global__ void __launch_bounds__(256) lossreduce_kernel(float* __restrict__ out_loss) {
    __shared__ float red[8];
    float s = 0.f;
    for (int i = threadIdx.x; i < NTOK; i += 256) s += g_rowloss[i];
    #pragma unroll
    for (int o = 16; o > 0; o >>= 1) s += __shfl_xor_sync(~0u, s, o);
    if ((threadIdx.x & 31) == 0) red[threadIdx.x >> 5] = s;
    __syncthreads();
    if (threadIdx.x == 0) {
        float t = 0.f;
        for (int w = 0; w < 8; w++) t += red[w];
        out_loss[0] = t * (1.0f / NTOK);
    }
}

// ---------------- host orchestration -----------------------------------------
extern "C" void kernel_launch(void* const* d_in, const int* in_sizes, int n_in,
                              void* d_out, int out_size) {
    const int*   idx      = (const int*)  d_in[0];
    const int*   targets  = (const int*)  d_in[1];
    const float* wte      = (const float*)d_in[2];
    const float* wpe      = (const float*)d_in[3];
    const float* ln1_s    = (const float*)d_in[4];
    const float* ln1_b    = (const float*)d_in[5];
    const float* attn_w   = (const float*)d_in[6];
    const float* attn_b   = (const float*)d_in[7];
    const float* proj_w   = (const float*)d_in[8];
    const float* proj_b   = (const float*)d_in[9];
    const float* ln2_s    = (const float*)d_in[10];
    const float* ln2_b    = (const float*)d_in[11];
    const float* fc_w     = (const float*)d_in[12];
    const float* fc_b     = (const float*)d_in[13];
    const float* proj2_w  = (const float*)d_in[14];
    const float* proj2_b  = (const float*)d_in[15];
    const float* lnf_s    = (const float*)d_in[16];
    const float* lnf_b    = (const float*)d_in[17];
    float* out = (float*)d_out;

    float *px, *ph, *pq, *py, *pm;
    cudaGetSymbolAddress((void**)&px, g_x);
    cudaGetSymbolAddress((void**)&ph, g_h);
    cudaGetSymbolAddress((void**)&pq, g_qkv);
    cudaGetSymbolAddress((void**)&py, g_y);
    cudaGetSymbolAddress((void**)&pm, g_m);

    embed_kernel<<<NTOK, 256>>>(idx, wte, wpe);

    for (int l = 0; l < NLAYER; l++) {
        const float* aw  = attn_w  + (size_t)l * DMODEL * 3 * DMODEL;
        const float* ab  = attn_b  + (size_t)l * 3 * DMODEL;
        const float* pw  = proj_w  + (size_t)l * DMODEL * DMODEL;
        const float* pb  = proj_b  + (size_t)l * DMODEL;
        const float* fw  = fc_w    + (size_t)l * DMODEL * 4 * DMODEL;
        const float* fb  = fc_b    + (size_t)l * 4 * DMODEL;
        const float* p2w = proj2_w + (size_t)l * 4 * DMODEL * DMODEL;
        const float* p2b = proj2_b + (size_t)l * DMODEL;

        ln_kernel<<<NTOK, 256>>>(px, ln1_s + l * DMODEL, ln1_b + l * DMODEL, ph);
        sgemm_kernel<false, 1><<<dim3(3 * DMODEL / 128, NTOK / 128), 256>>>(
            ph, aw, ab, pq, NTOK, 3 * DMODEL, DMODEL);
        attn_kernel<<<dim3(SEQ / 64, NHEAD, 2), 256>>>(py);
        sgemm_kernel<false, 3><<<dim3(DMODEL / 128, NTOK / 128), 256>>>(
            py, pw, pb, px, NTOK, DMODEL, DMODEL);
        ln_kernel<<<NTOK, 256>>>(px, ln2_s + l * DMODEL, ln2_b + l * DMODEL, ph);
        sgemm_kernel<false, 2><<<dim3(4 * DMODEL / 128, NTOK / 128), 256>>>(
            ph, fw, fb, pm, NTOK, 4 * DMODEL, DMODEL);
        sgemm_kernel<false, 3><<<dim3(DMODEL / 128, NTOK / 128), 256>>>(
            pm, p2w, p2b, px, NTOK, DMODEL, 4 * DMODEL);
    }

    ln_kernel<<<NTOK, 256>>>(px, lnf_s, lnf_b, ph);
    // logits = h @ wte^T  (wte is [V, D] row-major -> TRANSB)
    sgemm_kernel<true, 0><<<dim3((VOCAB + 127) / 128, NTOK / 128), 256>>>(
        ph, wte, (const float*)nullptr, out, NTOK, VOCAB, DMODEL);

    lossrow_kernel<<<NTOK, 256>>>(out, targets);
    lossreduce_kernel<<<1, 256>>>(out + (size_t)NTOK * VOCAB);
}

// round 3
// speedup vs baseline: 1.4336x; 1.4336x over previous
#include <cuda_runtime.h>
#include <cuda_bf16.h>
#include <math.h>
#include <stdint.h>

// Problem constants
#define NTOK 2048          // B*T
#define SEQ  1024
#define DMODEL 768
#define NHEAD 12
#define HDIM 64
#define NLAYER 8
#define VOCAB 50257
#define VPAD  50304        // 393*128

// ---------------- scratch (device globals; no allocation allowed) ------------
__device__ float g_x   [NTOK * DMODEL];
__device__ float g_h   [NTOK * DMODEL];
__device__ float g_qkv [NTOK * 3 * DMODEL];
__device__ float g_y   [NTOK * DMODEL];
__device__ float g_m   [NTOK * 4 * DMODEL];
__device__ float g_rowloss[NTOK];
// bf16 hi/lo planes
__device__ __nv_bfloat16 g_aH[NTOK * 4 * DMODEL];
__device__ __nv_bfloat16 g_aL[NTOK * 4 * DMODEL];
__device__ __nv_bfloat16 g_wTh[4 * DMODEL * DMODEL];   // max 3072x768 transposed weight
__device__ __nv_bfloat16 g_wTl[4 * DMODEL * DMODEL];
__device__ __nv_bfloat16 g_wteH[(size_t)VPAD * DMODEL];
__device__ __nv_bfloat16 g_wteL[(size_t)VPAD * DMODEL];

// ---------------- helpers -----------------------------------------------------
__device__ __forceinline__ uint32_t smem_u32(const void* p) {
    uint32_t a;
    asm("{ .reg .u64 t; cvta.to.shared.u64 t, %1; cvt.u32.u64 %0, t; }" : "=r"(a) : "l"(p));
    return a;
}

#define CP_ASYNC16(s, g) \
    asm volatile("cp.async.cg.shared.global [%0], [%1], 16;" :: "r"(s), "l"(g) : "memory")
#define CP_COMMIT() asm volatile("cp.async.commit_group;" ::: "memory")

__device__ __forceinline__ void ldsm4(uint32_t r[4], uint32_t addr) {
    asm volatile("ldmatrix.sync.aligned.m8n8.x4.shared.b16 {%0,%1,%2,%3}, [%4];"
        : "=r"(r[0]), "=r"(r[1]), "=r"(r[2]), "=r"(r[3]) : "r"(addr));
}
__device__ __forceinline__ void mma_bf16(float c[4], const uint32_t a[4],
                                         uint32_t b0, uint32_t b1) {
    asm volatile("mma.sync.aligned.m16n8k16.row.col.f32.bf16.bf16.f32 "
        "{%0,%1,%2,%3}, {%4,%5,%6,%7}, {%8,%9}, {%0,%1,%2,%3};"
        : "+f"(c[0]), "+f"(c[1]), "+f"(c[2]), "+f"(c[3])
        : "r"(a[0]), "r"(a[1]), "r"(a[2]), "r"(a[3]), "r"(b0), "r"(b1));
}

__device__ __forceinline__ float gelu_f(float x) {
    const float c = 0.7978845608028654f;
    float x3 = x * x * x;
    return 0.5f * x * (1.0f + tanhf(c * (x + 0.044715f * x3)));
}

// ---------------- HMMA bf16x3 GEMM --------------------------------------------
// C[M,N] = A[M,K] * B^T (B stored [N,K] hi/lo bf16). CTA tile 128x128, KC=64.
// EPI: 0 plain, 1 +bias, 2 gelu(+bias), 3 residual C += acc + bias
#define KC 64
#define PLANE_B 16384              // 128 rows * 128 bytes
#define STAGE_B (4 * PLANE_B)      // Ah, Al, Bh, Bl
#define GSMEM_NEED (2 * STAGE_B + 128)

template <int EPI, bool NPRED>
__global__ void __launch_bounds__(256, 1)
gemm_tc(const __nv_bfloat16* __restrict__ Ah, const __nv_bfloat16* __restrict__ Al,
        const __nv_bfloat16* __restrict__ Bh, const __nv_bfloat16* __restrict__ Bl,
        const float* __restrict__ bias, float* __restrict__ C, int N, int K) {
    extern __shared__ char dsm[];
    uint32_t sb = (smem_u32(dsm) + 127) & ~127u;

    const int tid = threadIdx.x;
    const int wid = tid >> 5, lid = tid & 31;
    const long bm = (long)blockIdx.x * 128;   // x = M tiles (L2 reuse of B across CTAs)
    const long bn = (long)blockIdx.y * 128;
    const int wm = (wid >> 2) * 64;           // warp M offset in tile
    const int wn = (wid & 3) * 32;            // warp N offset in tile
    const int lrow = lid & 15, lg = lid >> 4;

    const int nch = K / KC;

    // ---- stage loader (cp.async, 16 xfers per thread) ----
    auto load_stage = [&](int c, int st) {
        uint32_t stb = sb + st * STAGE_B;
        int kc0 = c * KC;
        #pragma unroll
        for (int i = 0; i < 4; i++) {
            int u = tid + 256 * i;            // 0..1023
            int row = u >> 3, g = u & 7;
            uint32_t so = stb + row * 128 + ((g ^ (row & 7)) << 4);
            long ka = (bm + row) * (long)K + kc0 + g * 8;
            long kb = (bn + row) * (long)K + kc0 + g * 8;
            CP_ASYNC16(so,               Ah + ka);
            CP_ASYNC16(so + PLANE_B,     Al + ka);
            CP_ASYNC16(so + 2 * PLANE_B, Bh + kb);
            CP_ASYNC16(so + 3 * PLANE_B, Bl + kb);
        }
        CP_COMMIT();
    };

    float creg[4][4][4];
    #pragma unroll
    for (int a = 0; a < 4; a++)
        #pragma unroll
        for (int b = 0; b < 4; b++)
            #pragma unroll
            for (int k = 0; k < 4; k++) creg[a][b][k] = 0.f;

    load_stage(0, 0);
    load_stage(1, 1);

    for (int c = 0; c < nch; c++) {
        if (c + 1 < nch) { asm volatile("cp.async.wait_group 1;" ::: "memory"); }
        else             { asm volatile("cp.async.wait_group 0;" ::: "memory"); }
        __syncthreads();

        uint32_t stb = sb + (c & 1) * STAGE_B;
        #pragma unroll
        for (int ks = 0; ks < 4; ks++) {
            int g = 2 * ks + lg;
            uint32_t aH[4][4], aL[4][4], bH[2][4], bL[2][4];
            #pragma unroll
            for (int mi = 0; mi < 4; mi++) {
                int row = wm + mi * 16 + lrow;
                uint32_t off = row * 128 + ((g ^ (row & 7)) << 4);
                ldsm4(aH[mi], stb + off);
                ldsm4(aL[mi], stb + PLANE_B + off);
            }
            #pragma unroll
            for (int ng = 0; ng < 2; ng++) {
                int row = wn + ng * 16 + lrow;
                uint32_t off = row * 128 + ((g ^ (row & 7)) << 4);
                ldsm4(bH[ng], stb + 2 * PLANE_B + off);
                ldsm4(bL[ng], stb + 3 * PLANE_B + off);
            }
            #pragma unroll
            for (int mi = 0; mi < 4; mi++)
                #pragma unroll
                for (int ni = 0; ni < 4; ni++) {
                    int ng = ni >> 1, h = ni & 1;
                    mma_bf16(creg[mi][ni], aH[mi], bH[ng][h], bH[ng][h + 2]);
                    mma_bf16(creg[mi][ni], aH[mi], bL[ng][h], bL[ng][h + 2]);
                    mma_bf16(creg[mi][ni], aL[mi], bH[ng][h], bH[ng][h + 2]);
                }
        }
        __syncthreads();
        if (c + 2 < nch) load_stage(c + 2, c & 1);
    }

    // ---- epilogue ----
    int gid = lid >> 2, tin = lid & 3;
    #pragma unroll
    for (int mi = 0; mi < 4; mi++) {
        long row0 = bm + wm + mi * 16 + gid;
        long row1 = row0 + 8;
        #pragma unroll
        for (int ni = 0; ni < 4; ni++) {
            long col = bn + wn + ni * 8 + tin * 2;
            float b0 = 0.f, b1 = 0.f;
            if (EPI >= 1) { b0 = bias[col]; b1 = bias[col + 1]; }
            float v0 = creg[mi][ni][0] + b0;
            float v1 = creg[mi][ni][1] + b1;
            float v2 = creg[mi][ni][2] + b0;
            float v3 = creg[mi][ni][3] + b1;
            if (EPI == 2) { v0 = gelu_f(v0); v1 = gelu_f(v1); v2 = gelu_f(v2); v3 = gelu_f(v3); }
            if (NPRED) {
                if (col < N)     { C[row0 * N + col]     = v0; C[row1 * N + col]     = v2; }
                if (col + 1 < N) { C[row0 * N + col + 1] = v1; C[row1 * N + col + 1] = v3; }
            } else {
                size_t o0 = (size_t)row0 * N + col;
                size_t o1 = (size_t)row1 * N + col;
                if (EPI == 3) {
                    float2 c0 = *(float2*)&C[o0];
                    float2 c1 = *(float2*)&C[o1];
                    v0 += c0.x; v1 += c0.y; v2 += c1.x; v3 += c1.y;
                }
                *(float2*)&C[o0] = make_float2(v0, v1);
                *(float2*)&C[o1] = make_float2(v2, v3);
            }
        }
    }
}

// ---------------- conversion kernels -----------------------------------------
__global__ void cvt_act(const float* __restrict__ x, __nv_bfloat16* __restrict__ h,
                        __nv_bfloat16* __restrict__ l, int n) {
    int i = blockIdx.x * 256 + threadIdx.x;
    if (i >= n) return;
    float v = x[i];
    __nv_bfloat16 hb = __float2bfloat16(v);
    h[i] = hb;
    l[i] = __float2bfloat16(v - __bfloat162float(hb));
}

__global__ void cvt_wte_k(const float* __restrict__ wte) {
    size_t i = (size_t)blockIdx.x * 256 + threadIdx.x;
    if (i >= (size_t)VPAD * DMODEL) return;
    float v = (i < (size_t)VOCAB * DMODEL) ? wte[i] : 0.0f;
    __nv_bfloat16 hb = __float2bfloat16(v);
    g_wteH[i] = hb;
    g_wteL[i] = __float2bfloat16(v - __bfloat162float(hb));
}

// w [K,N] f32 -> out [N,K] bf16 hi/lo.  grid (N/32, K/32), block (32,8)
__global__ void cvt_wT(const float* __restrict__ w, __nv_bfloat16* __restrict__ th,
                       __nv_bfloat16* __restrict__ tl, int K, int N) {
    __shared__ float t[32][33];
    int n0 = blockIdx.x * 32, k0 = blockIdx.y * 32;
    int tx = threadIdx.x, ty = threadIdx.y;
    #pragma unroll
    for (int i = 0; i < 4; i++)
        t[ty + 8 * i][tx] = w[(size_t)(k0 + ty + 8 * i) * N + n0 + tx];
    __syncthreads();
    #pragma unroll
    for (int i = 0; i < 4; i++) {
        float v = t[tx][ty + 8 * i];
        __nv_bfloat16 hb = __float2bfloat16(v);
        size_t o = (size_t)(n0 + ty + 8 * i) * K + k0 + tx;
        th[o] = hb;
        tl[o] = __float2bfloat16(v - __bfloat162float(hb));
    }
}

// ---------------- embedding --------------------------------------------------
__global__ void embed_kernel(const int* __restrict__ idx,
                             const float* __restrict__ wte,
                             const float* __restrict__ wpe) {
    int row = blockIdx.x;
    int t = row & (SEQ - 1);
    int tok = idx[row];
    const float* we = wte + (size_t)tok * DMODEL;
    const float* wp = wpe + (size_t)t * DMODEL;
    float* xr = g_x + (size_t)row * DMODEL;
    for (int d = threadIdx.x; d < DMODEL; d += blockDim.x)
        xr[d] = we[d] + wp[d];
}

// ---------------- layernorm --------------------------------------------------
__global__ void __launch_bounds__(256) ln_kernel(const float* __restrict__ x,
                                                 const float* __restrict__ sc,
                                                 const float* __restrict__ bi,
                                                 float* __restrict__ out) {
    __shared__ float red[8];
    int row = blockIdx.x, tid = threadIdx.x;
    const float* xr = x + (size_t)row * DMODEL;
    float v0 = xr[tid], v1 = xr[tid + 256], v2 = xr[tid + 512];

    float s = v0 + v1 + v2;
    #pragma unroll
    for (int o = 16; o > 0; o >>= 1) s += __shfl_xor_sync(~0u, s, o);
    if ((tid & 31) == 0) red[tid >> 5] = s;
    __syncthreads();
    if (tid < 32) {
        float t = (tid < 8) ? red[tid] : 0.f;
        #pragma unroll
        for (int o = 4; o > 0; o >>= 1) t += __shfl_xor_sync(~0u, t, o);
        if (tid == 0) red[0] = t;
    }
    __syncthreads();
    float mu = red[0] * (1.0f / DMODEL);
    __syncthreads();

    float d0 = v0 - mu, d1 = v1 - mu, d2 = v2 - mu;
    float s2 = d0 * d0 + d1 * d1 + d2 * d2;
    #pragma unroll
    for (int o = 16; o > 0; o >>= 1) s2 += __shfl_xor_sync(~0u, s2, o);
    if ((tid & 31) == 0) red[tid >> 5] = s2;
    __syncthreads();
    if (tid < 32) {
        float t = (tid < 8) ? red[tid] : 0.f;
        #pragma unroll
        for (int o = 4; o > 0; o >>= 1) t += __shfl_xor_sync(~0u, t, o);
        if (tid == 0) red[0] = t;
    }
    __syncthreads();
    float var = red[0] * (1.0f / DMODEL);
    float rs = rsqrtf(var + 1e-5f);

    float* orow = out + (size_t)row * DMODEL;
    orow[tid]       = d0 * rs * sc[tid]       + bi[tid];
    orow[tid + 256] = d1 * rs * sc[tid + 256] + bi[tid + 256];
    orow[tid + 512] = d2 * rs * sc[tid + 512] + bi[tid + 512];
}

// ---------------- flash-style causal attention (fp32) ------------------------
__global__ void __launch_bounds__(256) attn_kernel(float* __restrict__ out) {
    __shared__ float qs[64][64];
    __shared__ float ks[32][64];
    __shared__ float vs[32][64];
    __shared__ float ps[64][32];

    int q0 = blockIdx.x * 64;
    int h = blockIdx.y;
    int b = blockIdx.z;
    int tid = threadIdx.x;
    int r = tid >> 2, j = tid & 3;
    int d0 = j * 16, c0 = j * 8;
    const float scale = 0.125f;

    {
        int lr = tid >> 2;
        int cc = (tid & 3) * 16;
        const float* src = g_qkv + (size_t)(b * SEQ + q0 + lr) * (3 * DMODEL) + h * HDIM + cc;
        #pragma unroll
        for (int i = 0; i < 4; i++) {
            float4 v = ((const float4*)src)[i];
            qs[lr][cc + i * 4 + 0] = v.x * scale;
            qs[lr][cc + i * 4 + 1] = v.y * scale;
            qs[lr][cc + i * 4 + 2] = v.z * scale;
            qs[lr][cc + i * 4 + 3] = v.w * scale;
        }
    }

    float oacc[16];
    #pragma unroll
    for (int d = 0; d < 16; d++) oacc[d] = 0.f;
    float mrun = -1e30f, lrun = 0.f;

    for (int kv0 = 0; kv0 < q0 + 64; kv0 += 32) {
        __syncthreads();
        {
            int lr2 = tid >> 3;
            int cc = (tid & 7) * 8;
            const float* ksrc = g_qkv + (size_t)(b * SEQ + kv0 + lr2) * (3 * DMODEL) + DMODEL + h * HDIM + cc;
            const float* vsrc = g_qkv + (size_t)(b * SEQ + kv0 + lr2) * (3 * DMODEL) + 2 * DMODEL + h * HDIM + cc;
            *(float4*)&ks[lr2][cc]     = ((const float4*)ksrc)[0];
            *(float4*)&ks[lr2][cc + 4] = ((const float4*)ksrc)[1];
            *(float4*)&vs[lr2][cc]     = ((const float4*)vsrc)[0];
            *(float4*)&vs[lr2][cc + 4] = ((const float4*)vsrc)[1];
        }
        __syncthreads();

        float sv[8];
        #pragma unroll
        for (int c = 0; c < 8; c++) {
            int ci = c0 + c;
            float a = 0.f;
            #pragma unroll 16
            for (int d = 0; d < 64; d++) a += qs[r][d] * ks[ci][d];
            sv[c] = (kv0 + ci <= q0 + r) ? a : -1e30f;
        }
        float tm = sv[0];
        #pragma unroll
        for (int c = 1; c < 8; c++) tm = fmaxf(tm, sv[c]);
        tm = fmaxf(tm, __shfl_xor_sync(~0u, tm, 1));
        tm = fmaxf(tm, __shfl_xor_sync(~0u, tm, 2));
        float mnew = fmaxf(mrun, tm);
        float alpha = __expf(mrun - mnew);
        float psum = 0.f;
        #pragma unroll
        for (int c = 0; c < 8; c++) {
            float p = __expf(sv[c] - mnew);
            ps[r][c0 + c] = p;
            psum += p;
        }
        psum += __shfl_xor_sync(~0u, psum, 1);
        psum += __shfl_xor_sync(~0u, psum, 2);
        lrun = lrun * alpha + psum;
        mrun = mnew;
        #pragma unroll
        for (int d = 0; d < 16; d++) oacc[d] *= alpha;
        __syncwarp();
        #pragma unroll 4
        for (int c = 0; c < 32; c++) {
            float p = ps[r][c];
            #pragma unroll
            for (int d = 0; d < 16; d++) oacc[d] += p * vs[c][d0 + d];
        }
    }

    float inv = 1.0f / lrun;
    float* orow = out + (size_t)(b * SEQ + q0 + r) * DMODEL + h * HDIM + d0;
    #pragma unroll
    for (int d = 0; d < 16; d++) orow[d] = oacc[d] * inv;
}

// ---------------- loss --------------------------------------------------------
__global__ void __launch_bounds__(256) lossrow_kernel(const float* __restrict__ logits,
                                                      const int* __restrict__ targets) {
    int row = blockIdx.x;
    const float* lr_ = logits + (size_t)row * VOCAB;
    float m = -1e30f, s = 0.f;
    for (int jv = threadIdx.x; jv < VOCAB; jv += 256) {
        float v = lr_[jv];
        if (v <= m) {
            s += __expf(v - m);
        } else {
            s = s * __expf(m - v) + 1.0f;
            m = v;
        }
    }
    __shared__ float sm[256], ss[256];
    sm[threadIdx.x] = m; ss[threadIdx.x] = s;
    __syncthreads();
    for (int st = 128; st > 0; st >>= 1) {
        if (threadIdx.x < st) {
            float ma = sm[threadIdx.x], sa = ss[threadIdx.x];
            float mb = sm[threadIdx.x + st], sb = ss[threadIdx.x + st];
            float M = fmaxf(ma, mb);
            ss[threadIdx.x] = sa * __expf(ma - M) + sb * __expf(mb - M);
            sm[threadIdx.x] = M;
        }
        __syncthreads();
    }
    if (threadIdx.x == 0) {
        float lse = sm[0] + logf(ss[0]);
        g_rowloss[row] = lse - lr_[targets[row]];
    }
}

__global__ void __launch_bounds__(256) lossreduce_kernel(float* __restrict__ out_loss) {
    __shared__ float red[8];
    float s = 0.f;
    for (int i = threadIdx.x; i < NTOK; i += 256) s += g_rowloss[i];
    #pragma unroll
    for (int o = 16; o > 0; o >>= 1) s += __shfl_xor_sync(~0u, s, o);
    if ((threadIdx.x & 31) == 0) red[threadIdx.x >> 5] = s;
    __syncthreads();
    if (threadIdx.x == 0) {
        float t = 0.f;
        for (int w = 0; w < 8; w++) t += red[w];
        out_loss[0] = t * (1.0f / NTOK);
    }
}

// ---------------- host orchestration -----------------------------------------
extern "C" void kernel_launch(void* const* d_in, const int* in_sizes, int n_in,
                              void* d_out, int out_size) {
    const int*   idx     = (const int*)  d_in[0];
    const int*   targets = (const int*)  d_in[1];
    const float* wte     = (const float*)d_in[2];
    const float* wpe     = (const float*)d_in[3];
    const float* ln1_s   = (const float*)d_in[4];
    const float* ln1_b   = (const float*)d_in[5];
    const float* attn_w  = (const float*)d_in[6];
    const float* attn_b  = (const float*)d_in[7];
    const float* proj_w  = (const float*)d_in[8];
    const float* proj_b  = (const float*)d_in[9];
    const float* ln2_s   = (const float*)d_in[10];
    const float* ln2_b   = (const float*)d_in[11];
    const float* fc_w    = (const float*)d_in[12];
    const float* fc_b    = (const float*)d_in[13];
    const float* proj2_w = (const float*)d_in[14];
    const float* proj2_b = (const float*)d_in[15];
    const float* lnf_s   = (const float*)d_in[16];
    const float* lnf_b   = (const float*)d_in[17];
    float* out = (float*)d_out;

    float *px, *ph, *pq, *py, *pm;
    __nv_bfloat16 *paH, *paL, *pwTh, *pwTl, *pwteH, *pwteL;
    cudaGetSymbolAddress((void**)&px, g_x);
    cudaGetSymbolAddress((void**)&ph, g_h);
    cudaGetSymbolAddress((void**)&pq, g_qkv);
    cudaGetSymbolAddress((void**)&py, g_y);
    cudaGetSymbolAddress((void**)&pm, g_m);
    cudaGetSymbolAddress((void**)&paH, g_aH);
    cudaGetSymbolAddress((void**)&paL, g_aL);
    cudaGetSymbolAddress((void**)&pwTh, g_wTh);
    cudaGetSymbolAddress((void**)&pwTl, g_wTl);
    cudaGetSymbolAddress((void**)&pwteH, g_wteH);
    cudaGetSymbolAddress((void**)&pwteL, g_wteL);

    cudaFuncSetAttribute(gemm_tc<1, false>, cudaFuncAttributeMaxDynamicSharedMemorySize, GSMEM_NEED);
    cudaFuncSetAttribute(gemm_tc<2, false>, cudaFuncAttributeMaxDynamicSharedMemorySize, GSMEM_NEED);
    cudaFuncSetAttribute(gemm_tc<3, false>, cudaFuncAttributeMaxDynamicSharedMemorySize, GSMEM_NEED);
    cudaFuncSetAttribute(gemm_tc<0, true>,  cudaFuncAttributeMaxDynamicSharedMemorySize, GSMEM_NEED);

    embed_kernel<<<NTOK, 256>>>(idx, wte, wpe);

    const int nA = NTOK * DMODEL;
    const int nM = NTOK * 4 * DMODEL;

    for (int l = 0; l < NLAYER; l++) {
        const float* aw  = attn_w  + (size_t)l * DMODEL * 3 * DMODEL;
        const float* ab  = attn_b  + (size_t)l * 3 * DMODEL;
        const float* pw  = proj_w  + (size_t)l * DMODEL * DMODEL;
        const float* pb  = proj_b  + (size_t)l * DMODEL;
        const float* fw  = fc_w    + (size_t)l * DMODEL * 4 * DMODEL;
        const float* fb  = fc_b    + (size_t)l * 4 * DMODEL;
        const float* p2w = proj2_w + (size_t)l * 4 * DMODEL * DMODEL;
        const float* p2b = proj2_b + (size_t)l * DMODEL;

        // --- attention block ---
        ln_kernel<<<NTOK, 256>>>(px, ln1_s + l * DMODEL, ln1_b + l * DMODEL, ph);
        cvt_act<<<(nA + 255) / 256, 256>>>(ph, paH, paL, nA);
        cvt_wT<<<dim3(3 * DMODEL / 32, DMODEL / 32), dim3(32, 8)>>>(aw, pwTh, pwTl, DMODEL, 3 * DMODEL);
        gemm_tc<1, false><<<dim3(NTOK / 128, 3 * DMODEL / 128), 256, GSMEM_NEED>>>(
            paH, paL, pwTh, pwTl, ab, pq, 3 * DMODEL, DMODEL);
        attn_kernel<<<dim3(SEQ / 64, NHEAD, 2), 256>>>(py);
        cvt_act<<<(nA + 255) / 256, 256>>>(py, paH, paL, nA);
        cvt_wT<<<dim3(DMODEL / 32, DMODEL / 32), dim3(32, 8)>>>(pw, pwTh, pwTl, DMODEL, DMODEL);
        gemm_tc<3, false><<<dim3(NTOK / 128, DMODEL / 128), 256, GSMEM_NEED>>>(
            paH, paL, pwTh, pwTl, pb, px, DMODEL, DMODEL);

        // --- MLP block ---
        ln_kernel<<<NTOK, 256>>>(px, ln2_s + l * DMODEL, ln2_b + l * DMODEL, ph);
        cvt_act<<<(nA + 255) / 256, 256>>>(ph, paH, paL, nA);
        cvt_wT<<<dim3(4 * DMODEL / 32, DMODEL / 32), dim3(32, 8)>>>(fw, pwTh, pwTl, DMODEL, 4 * DMODEL);
        gemm_tc<2, false><<<dim3(NTOK / 128, 4 * DMODEL / 128), 256, GSMEM_NEED>>>(
            paH, paL, pwTh, pwTl, fb, pm, 4 * DMODEL, DMODEL);
        cvt_act<<<(nM + 255) / 256, 256>>>(pm, paH, paL, nM);
        cvt_wT<<<dim3(DMODEL / 32, 4 * DMODEL / 32), dim3(32, 8)>>>(p2w, pwTh, pwTl, 4 * DMODEL, DMODEL);
        gemm_tc<3, false><<<dim3(NTOK / 128, DMODEL / 128), 256, GSMEM_NEED>>>(
            paH, paL, pwTh, pwTl, p2b, px, DMODEL, 4 * DMODEL);
    }

    // --- final LN + tied lm_head + loss ---
    ln_kernel<<<NTOK, 256>>>(px, lnf_s, lnf_b, ph);
    cvt_act<<<(nA + 255) / 256, 256>>>(ph, paH, paL, nA);
    {
        size_t nw = (size_t)VPAD * DMODEL;
        cvt_wte_k<<<(unsigned)((nw + 255) / 256), 256>>>(wte);
    }
    gemm_tc<0, true><<<dim3(NTOK / 128, VPAD / 128), 256, GSMEM_NEED>>>(
        paH, paL, pwteH, pwteL, (const float*)nullptr, out, VOCAB, DMODEL);

    lossrow_kernel<<<NTOK, 256>>>(out, targets);
    lossreduce_kernel<<<1, 256>>>(out + (size_t)NTOK * VOCAB);
}

// round 4
// speedup vs baseline: 4.5181x; 3.1516x over previous
#include <cuda_runtime.h>
#include <cuda_bf16.h>
#include <math.h>
#include <stdint.h>

// Problem constants
#define NTOK 2048          // B*T
#define SEQ  1024
#define DMODEL 768
#define NHEAD 12
#define HDIM 64
#define NLAYER 8
#define VOCAB 50257
#define VPAD  50304        // 393*128

// ---------------- scratch (device globals; no allocation allowed) ------------
__device__ float g_x[NTOK * DMODEL];
__device__ float g_rowloss[NTOK];
__device__ __nv_bfloat16 g_hH [NTOK * DMODEL];       // LN output hi/lo
__device__ __nv_bfloat16 g_hL [NTOK * DMODEL];
__device__ __nv_bfloat16 g_qkvH[NTOK * 3 * DMODEL];  // qkv hi/lo
__device__ __nv_bfloat16 g_qkvL[NTOK * 3 * DMODEL];
__device__ __nv_bfloat16 g_yH [NTOK * DMODEL];       // attention out hi/lo
__device__ __nv_bfloat16 g_yL [NTOK * DMODEL];
__device__ __nv_bfloat16 g_mH [NTOK * 4 * DMODEL];   // mlp hidden hi/lo
__device__ __nv_bfloat16 g_mL [NTOK * 4 * DMODEL];
__device__ __nv_bfloat16 g_wTh[4 * DMODEL * DMODEL]; // transposed weight hi/lo
__device__ __nv_bfloat16 g_wTl[4 * DMODEL * DMODEL];
__device__ __nv_bfloat16 g_wteH[(size_t)VPAD * DMODEL];
__device__ __nv_bfloat16 g_wteL[(size_t)VPAD * DMODEL];

// ---------------- helpers -----------------------------------------------------
__device__ __forceinline__ uint32_t smem_u32(const void* p) {
    uint32_t a;
    asm("{ .reg .u64 t; cvta.to.shared.u64 t, %1; cvt.u32.u64 %0, t; }" : "=r"(a) : "l"(p));
    return a;
}

#define CP_ASYNC16(s, g) \
    asm volatile("cp.async.cg.shared.global [%0], [%1], 16;" :: "r"(s), "l"(g) : "memory")
#define CP_COMMIT() asm volatile("cp.async.commit_group;" ::: "memory")

__device__ __forceinline__ void ldsm4(uint32_t r[4], uint32_t addr) {
    asm volatile("ldmatrix.sync.aligned.m8n8.x4.shared.b16 {%0,%1,%2,%3}, [%4];"
        : "=r"(r[0]), "=r"(r[1]), "=r"(r[2]), "=r"(r[3]) : "r"(addr));
}
__device__ __forceinline__ void ldsm4t(uint32_t r[4], uint32_t addr) {
    asm volatile("ldmatrix.sync.aligned.m8n8.x4.trans.shared.b16 {%0,%1,%2,%3}, [%4];"
        : "=r"(r[0]), "=r"(r[1]), "=r"(r[2]), "=r"(r[3]) : "r"(addr));
}
__device__ __forceinline__ void mma_bf16(float c[4], const uint32_t a[4],
                                         uint32_t b0, uint32_t b1) {
    asm volatile("mma.sync.aligned.m16n8k16.row.col.f32.bf16.bf16.f32 "
        "{%0,%1,%2,%3}, {%4,%5,%6,%7}, {%8,%9}, {%0,%1,%2,%3};"
        : "+f"(c[0]), "+f"(c[1]), "+f"(c[2]), "+f"(c[3])
        : "r"(a[0]), "r"(a[1]), "r"(a[2]), "r"(a[3]), "r"(b0), "r"(b1));
}

__device__ __forceinline__ float gelu_f(float x) {
    const float c = 0.7978845608028654f;
    float x3 = x * x * x;
    return 0.5f * x * (1.0f + tanhf(c * (x + 0.044715f * x3)));
}

// split two fp32 into packed bf16 hi-plane / lo-plane words (elem0 in low 16)
__device__ __forceinline__ void split_pack(float a, float b, uint32_t& hp, uint32_t& lp) {
    __nv_bfloat16 ha = __float2bfloat16(a), hb = __float2bfloat16(b);
    __nv_bfloat16 la = __float2bfloat16(a - __bfloat162float(ha));
    __nv_bfloat16 lb = __float2bfloat16(b - __bfloat162float(hb));
    hp = ((uint32_t)__bfloat16_as_ushort(hb) << 16) | __bfloat16_as_ushort(ha);
    lp = ((uint32_t)__bfloat16_as_ushort(lb) << 16) | __bfloat16_as_ushort(la);
}

// ---------------- HMMA bf16x3 GEMM --------------------------------------------
// C[M,N] = A[M,K] * B^T (B stored [N,K] hi/lo bf16). CTA tile 128x128, KC=64.
// EPI: 0 plain, 1 +bias, 2 gelu(+bias), 3 residual C += acc + bias (f32 only)
// OBF: write bf16 hi/lo planes (CH/CL) instead of f32 C
#define KC 64
#define PLANE_B 16384              // 128 rows * 128 bytes
#define STAGE_B (4 * PLANE_B)      // Ah, Al, Bh, Bl
#define GSMEM_NEED (2 * STAGE_B + 128)

template <int EPI, bool NPRED, bool OBF>
__global__ void __launch_bounds__(256, 1)
gemm_tc(const __nv_bfloat16* __restrict__ Ah, const __nv_bfloat16* __restrict__ Al,
        const __nv_bfloat16* __restrict__ Bh, const __nv_bfloat16* __restrict__ Bl,
        const float* __restrict__ bias, float* __restrict__ C,
        __nv_bfloat16* __restrict__ CH, __nv_bfloat16* __restrict__ CL,
        int N, int K) {
    extern __shared__ char dsm[];
    uint32_t sb = (smem_u32(dsm) + 127) & ~127u;

    const int tid = threadIdx.x;
    const int wid = tid >> 5, lid = tid & 31;
    const long bm = (long)blockIdx.x * 128;   // x = M tiles (L2 reuse of B)
    const long bn = (long)blockIdx.y * 128;
    const int wm = (wid >> 2) * 64;
    const int wn = (wid & 3) * 32;
    const int lrow = lid & 15, lg = lid >> 4;

    const int nch = K / KC;

    auto load_stage = [&](int c, int st) {
        uint32_t stb = sb + st * STAGE_B;
        int kc0 = c * KC;
        #pragma unroll
        for (int i = 0; i < 4; i++) {
            int u = tid + 256 * i;
            int row = u >> 3, g = u & 7;
            uint32_t so = stb + row * 128 + ((g ^ (row & 7)) << 4);
            long ka = (bm + row) * (long)K + kc0 + g * 8;
            long kb = (bn + row) * (long)K + kc0 + g * 8;
            CP_ASYNC16(so,               Ah + ka);
            CP_ASYNC16(so + PLANE_B,     Al + ka);
            CP_ASYNC16(so + 2 * PLANE_B, Bh + kb);
            CP_ASYNC16(so + 3 * PLANE_B, Bl + kb);
        }
        CP_COMMIT();
    };

    float creg[4][4][4];
    #pragma unroll
    for (int a = 0; a < 4; a++)
        #pragma unroll
        for (int b = 0; b < 4; b++)
            #pragma unroll
            for (int k = 0; k < 4; k++) creg[a][b][k] = 0.f;

    load_stage(0, 0);
    load_stage(1, 1);

    for (int c = 0; c < nch; c++) {
        if (c + 1 < nch) { asm volatile("cp.async.wait_group 1;" ::: "memory"); }
        else             { asm volatile("cp.async.wait_group 0;" ::: "memory"); }
        __syncthreads();

        uint32_t stb = sb + (c & 1) * STAGE_B;
        #pragma unroll
        for (int ks = 0; ks < 4; ks++) {
            int g = 2 * ks + lg;
            uint32_t aH[4][4], aL[4][4], bH[2][4], bL[2][4];
            #pragma unroll
            for (int mi = 0; mi < 4; mi++) {
                int row = wm + mi * 16 + lrow;
                uint32_t off = row * 128 + ((g ^ (row & 7)) << 4);
                ldsm4(aH[mi], stb + off);
                ldsm4(aL[mi], stb + PLANE_B + off);
            }
            #pragma unroll
            for (int ng = 0; ng < 2; ng++) {
                int row = wn + ng * 16 + lrow;
                uint32_t off = row * 128 + ((g ^ (row & 7)) << 4);
                ldsm4(bH[ng], stb + 2 * PLANE_B + off);
                ldsm4(bL[ng], stb + 3 * PLANE_B + off);
            }
            #pragma unroll
            for (int mi = 0; mi < 4; mi++)
                #pragma unroll
                for (int ni = 0; ni < 4; ni++) {
                    int ng = ni >> 1, h = ni & 1;
                    mma_bf16(creg[mi][ni], aH[mi], bH[ng][h], bH[ng][h + 2]);
                    mma_bf16(creg[mi][ni], aH[mi], bL[ng][h], bL[ng][h + 2]);
                    mma_bf16(creg[mi][ni], aL[mi], bH[ng][h], bH[ng][h + 2]);
                }
        }
        __syncthreads();
        if (c + 2 < nch) load_stage(c + 2, c & 1);
    }

    // ---- epilogue ----
    int gid = lid >> 2, tin = lid & 3;
    #pragma unroll
    for (int mi = 0; mi < 4; mi++) {
        long row0 = bm + wm + mi * 16 + gid;
        long row1 = row0 + 8;
        #pragma unroll
        for (int ni = 0; ni < 4; ni++) {
            long col = bn + wn + ni * 8 + tin * 2;
            float b0 = 0.f, b1 = 0.f;
            if (EPI >= 1) { b0 = bias[col]; b1 = bias[col + 1]; }
            float v0 = creg[mi][ni][0] + b0;
            float v1 = creg[mi][ni][1] + b1;
            float v2 = creg[mi][ni][2] + b0;
            float v3 = creg[mi][ni][3] + b1;
            if (EPI == 2) { v0 = gelu_f(v0); v1 = gelu_f(v1); v2 = gelu_f(v2); v3 = gelu_f(v3); }
            if (OBF) {
                uint32_t hp, lp;
                size_t o0 = (size_t)row0 * N + col;
                size_t o1 = (size_t)row1 * N + col;
                split_pack(v0, v1, hp, lp);
                *(uint32_t*)&CH[o0] = hp; *(uint32_t*)&CL[o0] = lp;
                split_pack(v2, v3, hp, lp);
                *(uint32_t*)&CH[o1] = hp; *(uint32_t*)&CL[o1] = lp;
            } else if (NPRED) {
                if (col < N)     { C[row0 * N + col]     = v0; C[row1 * N + col]     = v2; }
                if (col + 1 < N) { C[row0 * N + col + 1] = v1; C[row1 * N + col + 1] = v3; }
            } else {
                size_t o0 = (size_t)row0 * N + col;
                size_t o1 = (size_t)row1 * N + col;
                if (EPI == 3) {
                    float2 c0 = *(float2*)&C[o0];
                    float2 c1 = *(float2*)&C[o1];
                    v0 += c0.x; v1 += c0.y; v2 += c1.x; v3 += c1.y;
                }
                *(float2*)&C[o0] = make_float2(v0, v1);
                *(float2*)&C[o1] = make_float2(v2, v3);
            }
        }
    }
}

// ---------------- HMMA flash attention ----------------------------------------
// grid (SEQ/64, NHEAD, B), 128 threads (4 warps). Warp w owns q rows [w*16, w*16+16).
// smem: Qh(8K) Ql(8K) | stage{0,1}: Kh Kl Vh Vl (8K each)
#define ATT_SMEM (16384 + 2 * 32768 + 128)

__global__ void __launch_bounds__(128, 1)
attn_tc(const __nv_bfloat16* __restrict__ QKVh, const __nv_bfloat16* __restrict__ QKVl,
        __nv_bfloat16* __restrict__ Yh, __nv_bfloat16* __restrict__ Yl) {
    extern __shared__ char dsm[];
    uint32_t sb = (smem_u32(dsm) + 127) & ~127u;

    const int tid = threadIdx.x;
    const int wid = tid >> 5, lid = tid & 31;
    const int q0 = blockIdx.x * 64, h = blockIdx.y, b = blockIdx.z;
    const int wq = wid * 16;
    const int ntile = blockIdx.x + 1;
    const size_t rstride = 3 * DMODEL;

    auto ldplane = [&](uint32_t dst, const __nv_bfloat16* src) {
        #pragma unroll
        for (int i = 0; i < 4; i++) {
            int u = tid + 128 * i;
            int row = u >> 3, ch = u & 7;
            CP_ASYNC16(dst + row * 128 + ((ch ^ (row & 7)) << 4),
                       src + (size_t)row * rstride + ch * 8);
        }
    };
    auto ldstage = [&](int t) {
        uint32_t s = sb + 16384 + (t & 1) * 32768;
        size_t off = (size_t)(b * SEQ + t * 64) * rstride + h * HDIM;
        ldplane(s,         QKVh + off + DMODEL);
        ldplane(s + 8192,  QKVl + off + DMODEL);
        ldplane(s + 16384, QKVh + off + 2 * DMODEL);
        ldplane(s + 24576, QKVl + off + 2 * DMODEL);
        CP_COMMIT();
    };

    {
        size_t qoff = (size_t)(b * SEQ + q0) * rstride + h * HDIM;
        ldplane(sb,        QKVh + qoff);
        ldplane(sb + 8192, QKVl + qoff);
    }
    ldstage(0);

    float o[8][4];
    #pragma unroll
    for (int nb = 0; nb < 8; nb++)
        #pragma unroll
        for (int j = 0; j < 4; j++) o[nb][j] = 0.f;
    float mrun[2] = {-1e30f, -1e30f}, lrun[2] = {0.f, 0.f};

    for (int t = 0; t < ntile; t++) {
        asm volatile("cp.async.wait_group 0;" ::: "memory");
        __syncthreads();
        if (t + 1 < ntile) ldstage(t + 1);
        uint32_t kb = sb + 16384 + (t & 1) * 32768;

        // ---- S = Q K^T (x3) ----
        float s[8][4];
        #pragma unroll
        for (int nb = 0; nb < 8; nb++)
            #pragma unroll
            for (int j = 0; j < 4; j++) s[nb][j] = 0.f;

        #pragma unroll
        for (int ks = 0; ks < 4; ks++) {
            uint32_t qh[4], ql[4];
            {
                int r = wq + (lid & 15);
                uint32_t off = r * 128 + (((2 * ks + (lid >> 4)) ^ (r & 7)) << 4);
                ldsm4(qh, sb + off);
                ldsm4(ql, sb + 8192 + off);
            }
            #pragma unroll
            for (int ng = 0; ng < 4; ng++) {
                int r = ng * 16 + (lid & 15);
                uint32_t off = r * 128 + (((2 * ks + (lid >> 4)) ^ (r & 7)) << 4);
                uint32_t kh[4], kl[4];
                ldsm4(kh, kb + off);
                ldsm4(kl, kb + 8192 + off);
                mma_bf16(s[2 * ng],     qh, kh[0], kh[2]);
                mma_bf16(s[2 * ng],     qh, kl[0], kl[2]);
                mma_bf16(s[2 * ng],     ql, kh[0], kh[2]);
                mma_bf16(s[2 * ng + 1], qh, kh[1], kh[3]);
                mma_bf16(s[2 * ng + 1], qh, kl[1], kl[3]);
                mma_bf16(s[2 * ng + 1], ql, kh[1], kh[3]);
            }
        }

        // ---- scale + causal mask + online softmax ----
        #pragma unroll
        for (int nb = 0; nb < 8; nb++)
            #pragma unroll
            for (int j = 0; j < 4; j++) s[nb][j] *= 0.125f;

        if (t == blockIdx.x) {
            int r0g = q0 + wq + (lid >> 2);
            #pragma unroll
            for (int nb = 0; nb < 8; nb++) {
                int colg = t * 64 + nb * 8 + (lid & 3) * 2;
                if (colg     > r0g)     s[nb][0] = -1e30f;
                if (colg + 1 > r0g)     s[nb][1] = -1e30f;
                if (colg     > r0g + 8) s[nb][2] = -1e30f;
                if (colg + 1 > r0g + 8) s[nb][3] = -1e30f;
            }
        }

        #pragma unroll
        for (int half = 0; half < 2; half++) {
            float mx = -1e30f;
            #pragma unroll
            for (int nb = 0; nb < 8; nb++)
                mx = fmaxf(mx, fmaxf(s[nb][2 * half], s[nb][2 * half + 1]));
            mx = fmaxf(mx, __shfl_xor_sync(~0u, mx, 1));
            mx = fmaxf(mx, __shfl_xor_sync(~0u, mx, 2));
            float mn = fmaxf(mrun[half], mx);
            float al = __expf(mrun[half] - mn);
            mrun[half] = mn;
            float sum = 0.f;
            #pragma unroll
            for (int nb = 0; nb < 8; nb++) {
                float p0 = __expf(s[nb][2 * half]     - mn);
                float p1 = __expf(s[nb][2 * half + 1] - mn);
                s[nb][2 * half] = p0; s[nb][2 * half + 1] = p1;
                sum += p0 + p1;
            }
            lrun[half] = lrun[half] * al + sum;
            #pragma unroll
            for (int nb = 0; nb < 8; nb++) {
                o[nb][2 * half] *= al; o[nb][2 * half + 1] *= al;
            }
        }

        // ---- O += P V (x3) ----
        #pragma unroll
        for (int kk = 0; kk < 4; kk++) {
            uint32_t ph[4], pl[4];
            split_pack(s[2 * kk][0],     s[2 * kk][1],     ph[0], pl[0]);
            split_pack(s[2 * kk][2],     s[2 * kk][3],     ph[1], pl[1]);
            split_pack(s[2 * kk + 1][0], s[2 * kk + 1][1], ph[2], pl[2]);
            split_pack(s[2 * kk + 1][2], s[2 * kk + 1][3], ph[3], pl[3]);
            #pragma unroll
            for (int cc = 0; cc < 4; cc++) {
                int r = kk * 16 + (lid & 15);
                uint32_t off = r * 128 + (((2 * cc + (lid >> 4)) ^ (r & 7)) << 4);
                uint32_t vh[4], vl[4];
                ldsm4t(vh, kb + 16384 + off);
                ldsm4t(vl, kb + 24576 + off);
                mma_bf16(o[2 * cc],     ph, vh[0], vh[1]);
                mma_bf16(o[2 * cc],     pl, vh[0], vh[1]);
                mma_bf16(o[2 * cc],     ph, vl[0], vl[1]);
                mma_bf16(o[2 * cc + 1], ph, vh[2], vh[3]);
                mma_bf16(o[2 * cc + 1], pl, vh[2], vh[3]);
                mma_bf16(o[2 * cc + 1], ph, vl[2], vl[3]);
            }
        }
    }

    // ---- epilogue: normalize + write hi/lo ----
    float inv[2];
    #pragma unroll
    for (int half = 0; half < 2; half++) {
        float l = lrun[half];
        l += __shfl_xor_sync(~0u, l, 1);
        l += __shfl_xor_sync(~0u, l, 2);
        inv[half] = 1.0f / l;
    }
    int r0 = q0 + wq + (lid >> 2);
    #pragma unroll
    for (int nb = 0; nb < 8; nb++) {
        int col = h * HDIM + nb * 8 + (lid & 3) * 2;
        size_t o0 = (size_t)(b * SEQ + r0) * DMODEL + col;
        size_t o1 = (size_t)(b * SEQ + r0 + 8) * DMODEL + col;
        uint32_t hp, lp;
        split_pack(o[nb][0] * inv[0], o[nb][1] * inv[0], hp, lp);
        *(uint32_t*)&Yh[o0] = hp; *(uint32_t*)&Yl[o0] = lp;
        split_pack(o[nb][2] * inv[1], o[nb][3] * inv[1], hp, lp);
        *(uint32_t*)&Yh[o1] = hp; *(uint32_t*)&Yl[o1] = lp;
    }
}

// ---------------- conversion kernels (weights only) ----------------------------
__global__ void cvt_wte_k(const float* __restrict__ wte) {
    size_t i = (size_t)blockIdx.x * 256 + threadIdx.x;
    if (i >= (size_t)VPAD * DMODEL) return;
    float v = (i < (size_t)VOCAB * DMODEL) ? wte[i] : 0.0f;
    __nv_bfloat16 hb = __float2bfloat16(v);
    g_wteH[i] = hb;
    g_wteL[i] = __float2bfloat16(v - __bfloat162float(hb));
}

// w [K,N] f32 -> out [N,K] bf16 hi/lo.  grid (N/32, K/32), block (32,8)
__global__ void cvt_wT(const float* __restrict__ w, __nv_bfloat16* __restrict__ th,
                       __nv_bfloat16* __restrict__ tl, int K, int N) {
    __shared__ float t[32][33];
    int n0 = blockIdx.x * 32, k0 = blockIdx.y * 32;
    int tx = threadIdx.x, ty = threadIdx.y;
    #pragma unroll
    for (int i = 0; i < 4; i++)
        t[ty + 8 * i][tx] = w[(size_t)(k0 + ty + 8 * i) * N + n0 + tx];
    __syncthreads();
    #pragma unroll
    for (int i = 0; i < 4; i++) {
        float v = t[tx][ty + 8 * i];
        __nv_bfloat16 hb = __float2bfloat16(v);
        size_t o = (size_t)(n0 + ty + 8 * i) * K + k0 + tx;
        th[o] = hb;
        tl[o] = __float2bfloat16(v - __bfloat162float(hb));
    }
}

// ---------------- embedding --------------------------------------------------
__global__ void embed_kernel(const int* __restrict__ idx,
                             const float* __restrict__ wte,
                             const float* __restrict__ wpe) {
    int row = blockIdx.x;
    int t = row & (SEQ - 1);
    int tok = idx[row];
    const float* we = wte + (size_t)tok * DMODEL;
    const float* wp = wpe + (size_t)t * DMODEL;
    float* xr = g_x + (size_t)row * DMODEL;
    for (int d = threadIdx.x; d < DMODEL; d += blockDim.x)
        xr[d] = we[d] + wp[d];
}

// ---------------- layernorm (writes bf16 hi/lo planes) -----------------------
__global__ void __launch_bounds__(256) ln_kernel(const float* __restrict__ x,
                                                 const float* __restrict__ sc,
                                                 const float* __restrict__ bi,
                                                 __nv_bfloat16* __restrict__ outH,
                                                 __nv_bfloat16* __restrict__ outL) {
    __shared__ float red[8];
    int row = blockIdx.x, tid = threadIdx.x;
    const float* xr = x + (size_t)row * DMODEL;
    float v0 = xr[tid], v1 = xr[tid + 256], v2 = xr[tid + 512];

    float s = v0 + v1 + v2;
    #pragma unroll
    for (int o = 16; o > 0; o >>= 1) s += __shfl_xor_sync(~0u, s, o);
    if ((tid & 31) == 0) red[tid >> 5] = s;
    __syncthreads();
    if (tid < 32) {
        float t = (tid < 8) ? red[tid] : 0.f;
        #pragma unroll
        for (int o = 4; o > 0; o >>= 1) t += __shfl_xor_sync(~0u, t, o);
        if (tid == 0) red[0] = t;
    }
    __syncthreads();
    float mu = red[0] * (1.0f / DMODEL);
    __syncthreads();

    float d0 = v0 - mu, d1 = v1 - mu, d2 = v2 - mu;
    float s2 = d0 * d0 + d1 * d1 + d2 * d2;
    #pragma unroll
    for (int o = 16; o > 0; o >>= 1) s2 += __shfl_xor_sync(~0u, s2, o);
    if ((tid & 31) == 0) red[tid >> 5] = s2;
    __syncthreads();
    if (tid < 32) {
        float t = (tid < 8) ? red[tid] : 0.f;
        #pragma unroll
        for (int o = 4; o > 0; o >>= 1) t += __shfl_xor_sync(~0u, t, o);
        if (tid == 0) red[0] = t;
    }
    __syncthreads();
    float var = red[0] * (1.0f / DMODEL);
    float rs = rsqrtf(var + 1e-5f);

    size_t base = (size_t)row * DMODEL;
    #pragma unroll
    for (int e = 0; e < 3; e++) {
        float d = (e == 0) ? d0 : (e == 1) ? d1 : d2;
        int c = tid + 256 * e;
        float v = d * rs * sc[c] + bi[c];
        __nv_bfloat16 hb = __float2bfloat16(v);
        outH[base + c] = hb;
        outL[base + c] = __float2bfloat16(v - __bfloat162float(hb));
    }
}

// ---------------- loss --------------------------------------------------------
__global__ void __launch_bounds__(256) lossrow_kernel(const float* __restrict__ logits,
                                                      const int* __restrict__ targets) {
    int row = blockIdx.x;
    const float* lr_ = logits + (size_t)row * VOCAB;
    float m = -1e30f, s = 0.f;
    for (int jv = threadIdx.x; jv < VOCAB; jv += 256) {
        float v = lr_[jv];
        if (v <= m) {
            s += __expf(v - m);
        } else {
            s = s * __expf(m - v) + 1.0f;
            m = v;
        }
    }
    __shared__ float sm[256], ss[256];
    sm[threadIdx.x] = m; ss[threadIdx.x] = s;
    __syncthreads();
    for (int st = 128; st > 0; st >>= 1) {
        if (threadIdx.x < st) {
            float ma = sm[threadIdx.x], sa = ss[threadIdx.x];
            float mb = sm[threadIdx.x + st], sb = ss[threadIdx.x + st];
            float M = fmaxf(ma, mb);
            ss[threadIdx.x] = sa * __expf(ma - M) + sb * __expf(mb - M);
            sm[threadIdx.x] = M;
        }
        __syncthreads();
    }
    if (threadIdx.x == 0) {
        float lse = sm[0] + logf(ss[0]);
        g_rowloss[row] = lse - lr_[targets[row]];
    }
}

__global__ void __launch_bounds__(256) lossreduce_kernel(float* __restrict__ out_loss) {
    __shared__ float red[8];
    float s = 0.f;
    for (int i = threadIdx.x; i < NTOK; i += 256) s += g_rowloss[i];
    #pragma unroll
    for (int o = 16; o > 0; o >>= 1) s += __shfl_xor_sync(~0u, s, o);
    if ((threadIdx.x & 31) == 0) red[threadIdx.x >> 5] = s;
    __syncthreads();
    if (threadIdx.x == 0) {
        float t = 0.f;
        for (int w = 0; w < 8; w++) t += red[w];
        out_loss[0] = t * (1.0f / NTOK);
    }
}

// ---------------- host orchestration -----------------------------------------
extern "C" void kernel_launch(void* const* d_in, const int* in_sizes, int n_in,
                              void* d_out, int out_size) {
    const int*   idx     = (const int*)  d_in[0];
    const int*   targets = (const int*)  d_in[1];
    const float* wte     = (const float*)d_in[2];
    const float* wpe     = (const float*)d_in[3];
    const float* ln1_s   = (const float*)d_in[4];
    const float* ln1_b   = (const float*)d_in[5];
    const float* attn_w  = (const float*)d_in[6];
    const float* attn_b  = (const float*)d_in[7];
    const float* proj_w  = (const float*)d_in[8];
    const float* proj_b  = (const float*)d_in[9];
    const float* ln2_s   = (const float*)d_in[10];
    const float* ln2_b   = (const float*)d_in[11];
    const float* fc_w    = (const float*)d_in[12];
    const float* fc_b    = (const float*)d_in[13];
    const float* proj2_w = (const float*)d_in[14];
    const float* proj2_b = (const float*)d_in[15];
    const float* lnf_s   = (const float*)d_in[16];
    const float* lnf_b   = (const float*)d_in[17];
    float* out = (float*)d_out;

    float* px;
    __nv_bfloat16 *phH, *phL, *pqH, *pqL, *pyH, *pyL, *pmH, *pmL;
    __nv_bfloat16 *pwTh, *pwTl, *pwteH, *pwteL;
    cudaGetSymbolAddress((void**)&px, g_x);
    cudaGetSymbolAddress((void**)&phH, g_hH);
    cudaGetSymbolAddress((void**)&phL, g_hL);
    cudaGetSymbolAddress((void**)&pqH, g_qkvH);
    cudaGetSymbolAddress((void**)&pqL, g_qkvL);
    cudaGetSymbolAddress((void**)&pyH, g_yH);
    cudaGetSymbolAddress((void**)&pyL, g_yL);
    cudaGetSymbolAddress((void**)&pmH, g_mH);
    cudaGetSymbolAddress((void**)&pmL, g_mL);
    cudaGetSymbolAddress((void**)&pwTh, g_wTh);
    cudaGetSymbolAddress((void**)&pwTl, g_wTl);
    cudaGetSymbolAddress((void**)&pwteH, g_wteH);
    cudaGetSymbolAddress((void**)&pwteL, g_wteL);

    cudaFuncSetAttribute(gemm_tc<1, false, true>,  cudaFuncAttributeMaxDynamicSharedMemorySize, GSMEM_NEED);
    cudaFuncSetAttribute(gemm_tc<2, false, true>,  cudaFuncAttributeMaxDynamicSharedMemorySize, GSMEM_NEED);
    cudaFuncSetAttribute(gemm_tc<3, false, false>, cudaFuncAttributeMaxDynamicSharedMemorySize, GSMEM_NEED);
    cudaFuncSetAttribute(gemm_tc<0, true, false>,  cudaFuncAttributeMaxDynamicSharedMemorySize, GSMEM_NEED);
    cudaFuncSetAttribute(attn_tc, cudaFuncAttributeMaxDynamicSharedMemorySize, ATT_SMEM);

    embed_kernel<<<NTOK, 256>>>(idx, wte, wpe);

    for (int l = 0; l < NLAYER; l++) {
        const float* aw  = attn_w  + (size_t)l * DMODEL * 3 * DMODEL;
        const float* ab  = attn_b  + (size_t)l * 3 * DMODEL;
        const float* pw  = proj_w  + (size_t)l * DMODEL * DMODEL;
        const float* pb  = proj_b  + (size_t)l * DMODEL;
        const float* fw  = fc_w    + (size_t)l * DMODEL * 4 * DMODEL;
        const float* fb  = fc_b    + (size_t)l * 4 * DMODEL;
        const float* p2w = proj2_w + (size_t)l * 4 * DMODEL * DMODEL;
        const float* p2b = proj2_b + (size_t)l * DMODEL;

        // --- attention block ---
        ln_kernel<<<NTOK, 256>>>(px, ln1_s + l * DMODEL, ln1_b + l * DMODEL, phH, phL);
        cvt_wT<<<dim3(3 * DMODEL / 32, DMODEL / 32), dim3(32, 8)>>>(aw, pwTh, pwTl, DMODEL, 3 * DMODEL);
        gemm_tc<1, false, true><<<dim3(NTOK / 128, 3 * DMODEL / 128), 256, GSMEM_NEED>>>(
            phH, phL, pwTh, pwTl, ab, nullptr, pqH, pqL, 3 * DMODEL, DMODEL);
        attn_tc<<<dim3(SEQ / 64, NHEAD, 2), 128, ATT_SMEM>>>(pqH, pqL, pyH, pyL);
        cvt_wT<<<dim3(DMODEL / 32, DMODEL / 32), dim3(32, 8)>>>(pw, pwTh, pwTl, DMODEL, DMODEL);
        gemm_tc<3, false, false><<<dim3(NTOK / 128, DMODEL / 128), 256, GSMEM_NEED>>>(
            pyH, pyL, pwTh, pwTl, pb, px, nullptr, nullptr, DMODEL, DMODEL);

        // --- MLP block ---
        ln_kernel<<<NTOK, 256>>>(px, ln2_s + l * DMODEL, ln2_b + l * DMODEL, phH, phL);
        cvt_wT<<<dim3(4 * DMODEL / 32, DMODEL / 32), dim3(32, 8)>>>(fw, pwTh, pwTl, DMODEL, 4 * DMODEL);
        gemm_tc<2, false, true><<<dim3(NTOK / 128, 4 * DMODEL / 128), 256, GSMEM_NEED>>>(
            phH, phL, pwTh, pwTl, fb, nullptr, pmH, pmL, 4 * DMODEL, DMODEL);
        cvt_wT<<<dim3(DMODEL / 32, 4 * DMODEL / 32), dim3(32, 8)>>>(p2w, pwTh, pwTl, 4 * DMODEL, DMODEL);
        gemm_tc<3, false, false><<<dim3(NTOK / 128, DMODEL / 128), 256, GSMEM_NEED>>>(
            pmH, pmL, pwTh, pwTl, p2b, px, nullptr, nullptr, DMODEL, 4 * DMODEL);
    }

    // --- final LN + tied lm_head + loss ---
    ln_kernel<<<NTOK, 256>>>(px, lnf_s, lnf_b, phH, phL);
    {
        size_t nw = (size_t)VPAD * DMODEL;
        cvt_wte_k<<<(unsigned)((nw + 255) / 256), 256>>>(wte);
    }
    gemm_tc<0, true, false><<<dim3(NTOK / 128, VPAD / 128), 256, GSMEM_NEED>>>(
        phH, phL, pwteH, pwteL, nullptr, out, nullptr, nullptr, VOCAB, DMODEL);

    lossrow_kernel<<<NTOK, 256>>>(out, targets);
    lossreduce_kernel<<<1, 256>>>(out + (size_t)NTOK * VOCAB);
}